// round 15
// baseline (speedup 1.0000x reference)
#include <cuda_runtime.h>

// Problem constants (fixed by the reference: N=16, C=19, H=W=512)
#define NCLS 19
#define NIMG 16
#define HWPX (512 * 512)          // pixels per image = 262144
#define NF4  (HWPX / 4)           // float4s per class plane = 65536
#define EPSV 1e-6f

#define BLK_PER_IMG 37            // 37 * 16 = 592 = 148 SMs * 4 blocks: one wave
#define STRIDE4 (BLK_PER_IMG * 256)

// Scratch: per-(image,class) counters. Zero at module load; the finalize
// kernel reads them with plain loads and rezeros with plain stores (kernel
// boundary orders hist's atomics before finalize's loads), so every graph
// replay starts from zeros. No allocations anywhere.
__device__ unsigned int g_pred [NIMG * NCLS];
__device__ unsigned int g_targ [NIMG * NCLS];
__device__ unsigned int g_inter[NIMG * NCLS];

// ---------------------------------------------------------------------------
// Kernel 1: persistent per-pixel argmax over C=19 + per-image histograms.
// grid = (37, 16) = 592 blocks -> exactly one wave at 4 blocks/SM (60 regs,
// natural allocation — no launch_bounds occupancy cap: R14 showed capping to
// 5 blocks/SM spills and costs ~3.5us). Each block owns one image and
// grid-strides over its plane; shared histograms flushed ONCE per block
// (global ATOMG traffic cut 7x vs the 4096-block version). No multi-wave
// launch/drain overhead (~1.3us per wave transition x 6 waves saved).
// ---------------------------------------------------------------------------
__global__ void __launch_bounds__(256)
miou_hist_kernel(const float* __restrict__ preds,
                 const float* __restrict__ targets) {
    __shared__ unsigned int sp[NCLS];
    __shared__ unsigned int st[NCLS];
    __shared__ unsigned int si[NCLS];

    const int t = threadIdx.x;
    if (t < NCLS) { sp[t] = 0u; st[t] = 0u; si[t] = 0u; }
    __syncthreads();

    const int n = blockIdx.y;
    const float4* __restrict__ p4 =
        (const float4*)(preds   + (size_t)n * NCLS * HWPX);
    const float4* __restrict__ q4 =
        (const float4*)(targets + (size_t)n * NCLS * HWPX);

    // Grid-stride over the plane's 65536 float4s: i0 in [0, 9472), 6-7 iters.
    for (int i = blockIdx.x * 256 + t; i < NF4; i += STRIDE4) {
        float bpv[4], btv[4];
        int   bpi[4], bti[4];
#pragma unroll
        for (int j = 0; j < 4; j++) {
            bpv[j] = -3.4e38f; btv[j] = -3.4e38f; bpi[j] = 0; bti[j] = 0;
        }

#pragma unroll
        for (int c = 0; c < NCLS; c++) {
            const size_t off = (size_t)c * NF4 + i;
            float4 pv = p4[off];
            float4 tv = q4[off];
            float pa[4] = {pv.x, pv.y, pv.z, pv.w};
            float ta[4] = {tv.x, tv.y, tv.z, tv.w};
#pragma unroll
            for (int j = 0; j < 4; j++) {
                if (pa[j] > bpv[j]) { bpv[j] = pa[j]; bpi[j] = c; }  // strict >: first-index argmax
                if (ta[j] > btv[j]) { btv[j] = ta[j]; bti[j] = c; }
            }
        }

#pragma unroll
        for (int j = 0; j < 4; j++) {
            atomicAdd(&sp[bpi[j]], 1u);
            atomicAdd(&st[bti[j]], 1u);
            if (bpi[j] == bti[j]) atomicAdd(&si[bpi[j]], 1u);
        }
    }
    __syncthreads();

    // One flush per block (592 blocks x 57 atomics total).
    if (t < NCLS) {
        if (sp[t]) atomicAdd(&g_pred [n * NCLS + t], sp[t]);
        if (st[t]) atomicAdd(&g_targ [n * NCLS + t], st[t]);
        if (si[t]) atomicAdd(&g_inter[n * NCLS + t], si[t]);
    }
}

// ---------------------------------------------------------------------------
// Kernel 2: finalize + rezero (R14-measured 4.5us). One block, 320 threads.
// Plain loads (kernel boundary makes hist's atomics visible) and plain
// zero-stores for the next graph replay — no ATOMG round trips.
// out = mean_n mean_c ( (inter+eps)/(union+eps) * w[c] ) = sum / (N*C)
// ---------------------------------------------------------------------------
__global__ void __launch_bounds__(320)
miou_final_kernel(const float* __restrict__ w, float* __restrict__ out) {
    const int t = threadIdx.x;
    float v = 0.0f;
    if (t < NIMG * NCLS) {
        const int c = t % NCLS;
        float inter = (float)g_inter[t];
        float pc    = (float)g_pred[t];
        float tc    = (float)g_targ[t];
        g_inter[t] = 0u; g_pred[t] = 0u; g_targ[t] = 0u;   // rezero for next replay
        float uni  = pc + tc - inter;
        v = (inter + EPSV) / (uni + EPSV) * w[c];
    }

    // block reduction: warp shuffle then shared (10 warps)
    __shared__ float warp_sums[10];
#pragma unroll
    for (int o = 16; o > 0; o >>= 1)
        v += __shfl_down_sync(0xFFFFFFFFu, v, o);
    if ((t & 31) == 0) warp_sums[t >> 5] = v;
    __syncthreads();
    if (t < 32) {
        float s = (t < 10) ? warp_sums[t] : 0.0f;
#pragma unroll
        for (int o = 8; o > 0; o >>= 1)
            s += __shfl_down_sync(0xFFFFFFFFu, s, o);
        if (t == 0) out[0] = s / (float)(NIMG * NCLS);
    }
}

// ---------------------------------------------------------------------------
extern "C" void kernel_launch(void* const* d_in, const int* in_sizes, int n_in,
                              void* d_out, int out_size) {
    const float* preds   = (const float*)d_in[0];
    const float* targets = (const float*)d_in[1];
    const float* weights = (const float*)d_in[2];
    float* out = (float*)d_out;

    dim3 grid(BLK_PER_IMG, NIMG);   // 592 blocks: one full wave, persistent
    miou_hist_kernel<<<grid, 256>>>(preds, targets);
    miou_final_kernel<<<1, 320>>>(weights, out);
}